// round 13
// baseline (speedup 1.0000x reference)
#include <cuda_runtime.h>
#include <math.h>
#include <stdint.h>

// ---- problem constants ----
#define Bg   64
#define Nn   1024
#define Dd   128
#define EPG  8192
#define NTOT (Bg*Nn)      // 65536
#define ETOT (Bg*EPG)     // 524288
#define KP   820          // kept nodes per graph
#define BK   (Bg*KP)      // 52480
#define NEGS 0.2f
#define LAMBDA 1.0f
#define TJ   8            // columns per sparsemax tile
#define SHP  9            // shared pitch (bank-conflict free)
#define NQ   26           // ceil(KP/32)
#define CAP  64           // bucket capacity (P(deg>=48) ~ 5e-15)

// ---- device scratch ----
__device__ int    g_cnt_out[NTOT];
__device__ int    g_cnt_in[NTOT];
__device__ float  g_sn[NTOT];
__device__ float  g_dn[NTOT];
__device__ int    g_csr_src[NTOT * CAP];
__device__ float  g_csr_val[NTOT * CAP];
__device__ double g_wa_d[Dd];
__device__ float  g_score[NTOT];
__device__ int    g_mask[NTOT];
__device__ float  g_wsrc[BK];
__device__ float  g_wdst[BK];
__device__ int    g_pnode[BK];
__device__ int    g_cnt2[BK];
__device__ int    g2_row[BK * CAP];
__device__ float  g2_val[BK * CAP];

// XLA f32 tanh (Eigen rational approximation, as emitted by XLA's elemental IR)
__device__ __forceinline__ float tanh_xla(float x) {
    float ax = fabsf(x);
    float cx = fminf(fmaxf(x, -7.90531110763549805f), 7.90531110763549805f);
    float x2 = cx * cx;
    float p = fmaf(x2, -2.76076847742355e-16f, 2.00018790482477e-13f);
    p = fmaf(p, x2, -8.60467152213735e-11f);
    p = fmaf(p, x2, 5.12229709037114e-08f);
    p = fmaf(p, x2, 1.48572235717979e-05f);
    p = fmaf(p, x2, 6.37261928875436e-04f);
    p = fmaf(p, x2, 4.89352455891786e-03f);
    p = p * cx;
    float q = fmaf(x2, 1.19825839466702e-06f, 1.18534705686654e-04f);
    q = fmaf(q, x2, 2.26843463243900e-03f);
    q = fmaf(q, x2, 4.89352518554385e-03f);
    float r = p / q;
    return (ax < 0.0004f) ? x : r;
}

__global__ void __launch_bounds__(256) k_init() {
    int i = blockIdx.x * blockDim.x + threadIdx.x;
    if (i < NTOT) { g_cnt_out[i] = 0; g_cnt_in[i] = 0; g_mask[i] = -1; }
    if (i < BK)   { g_cnt2[i] = 0; }
}

// fused degree count + direct-bucket CSR-by-dst scatter
__global__ void __launch_bounds__(256) k_scatter1(const int* __restrict__ src,
                                                  const int* __restrict__ dst,
                                                  const float* __restrict__ ef) {
    int e = blockIdx.x * blockDim.x + threadIdx.x;
    if (e < ETOT) {
        int dn = dst[e], sn = src[e];
        atomicAdd(&g_cnt_out[sn], 1);
        int slot = atomicAdd(&g_cnt_in[dn], 1);
        if (slot < CAP) {
            g_csr_src[dn * CAP + slot] = sn;
            g_csr_val[dn * CAP + slot] = (sn != dn) ? ef[e] : 0.0f;  // e_feat*nonself
        }
    }
}

// fused: wa = W@a (double, blocks 0..15) + deg^-0.5 (blocks 16..271)
__global__ void __launch_bounds__(256) k_prep(const float* __restrict__ W,
                                              const float* __restrict__ a) {
    if (blockIdx.x < 16) {
        int warp = (blockIdx.x * 256 + threadIdx.x) >> 5;
        int lane = threadIdx.x & 31;
        if (warp < Dd) {
            double s = 0.0;
            for (int k = lane; k < Dd; k += 32)
                s += (double)W[warp * Dd + k] * (double)a[k];
            #pragma unroll
            for (int o = 16; o; o >>= 1) s += __shfl_xor_sync(0xffffffffu, s, o);
            if (lane == 0) g_wa_d[warp] = s;
        }
    } else {
        int i = (blockIdx.x - 16) * 256 + threadIdx.x;
        if (i < NTOT) {
            double od = (double)max(g_cnt_out[i], 1);
            double id = (double)max(g_cnt_in[i], 1);
            g_sn[i] = (float)(1.0 / sqrt(od));
            g_dn[i] = (float)(1.0 / sqrt(id));
        }
    }
}

// k_node v5: 4 warps per node — warp w owns elements [32w, 32w+32), lane = one
// f32 element. Per-element double accumulation keeps the identical term order
// (bit-identical (float)agg). The f32 |x - agg*dn| values are staged in shared
// and re-assembled by warp 0 in the exact XLA float2 lane layout + shfl tree.
__global__ void __launch_bounds__(256) k_node(const float* __restrict__ feat,
                                              float* __restrict__ out_xs) {
    __shared__ float  sm_t[2][Dd];
    __shared__ double sm_dp[2][4];
    int wid = threadIdx.x >> 5;     // 0..7
    int lane = threadIdx.x & 31;
    int local = wid >> 2;           // node slot within block (0/1)
    int w = wid & 3;                // quarter-row index
    int node = blockIdx.x * 2 + local;   // grid = NTOT/2 exactly
    int el = w * 32 + lane;
    float fv = feat[(size_t)node * Dd + el];
    double d = 0.0;
    int cnt = g_cnt_in[node]; if (cnt > CAP) cnt = CAP;
    int base = node * CAP;
    for (int p0 = 0; p0 < cnt; p0 += 8) {
        int m = cnt - p0; if (m > 8) m = 8;
        int sbuf[8]; float vbuf[8];
        #pragma unroll
        for (int t = 0; t < 8; t++) {
            sbuf[t] = (t < m) ? g_csr_src[base + p0 + t] : 0;
            vbuf[t] = (t < m) ? g_csr_val[base + p0 + t] : 0.f;
        }
        float snb[8], fbuf[8];
        #pragma unroll
        for (int t = 0; t < 8; t++)
            snb[t] = (vbuf[t] != 0.f) ? g_sn[sbuf[t]] : 0.f;
        #pragma unroll
        for (int t = 0; t < 8; t++)
            fbuf[t] = (vbuf[t] != 0.f) ? feat[(size_t)sbuf[t] * Dd + el] : 0.f;
        #pragma unroll
        for (int t = 0; t < 8; t++) {
            if (vbuf[t] != 0.f)
                d += (double)((fbuf[t] * snb[t]) * vbuf[t]);
        }
    }
    float dnf = g_dn[node];
    sm_t[local][el] = fabsf(fv - ((float)d) * dnf);
    // dp partial for this quarter (double; re-association ~1e-16 rel, safe)
    double dp = (double)fv * g_wa_d[el];
    #pragma unroll
    for (int o = 16; o; o >>= 1)
        dp += __shfl_xor_sync(0xffffffffu, dp, o);
    if (lane == 0) sm_dp[local][w] = dp;
    __syncthreads();
    if (w == 0) {
        // exact XLA tree: lane L holds {2L,2L+1} then {64+2L,65+2L}
        float t0 = sm_t[local][2 * lane];
        float t1 = sm_t[local][2 * lane + 1];
        float t2 = sm_t[local][64 + 2 * lane];
        float t3 = sm_t[local][65 + 2 * lane];
        float acc = ((t0 + t1) + t2) + t3;
        #pragma unroll
        for (int o = 16; o; o >>= 1)
            acc += __shfl_down_sync(0xffffffffu, acc, o);
        if (lane == 0) {
            double dpd = ((sm_dp[local][0] + sm_dp[local][1])
                        + sm_dp[local][2]) + sm_dp[local][3];
            float lr = (float)dpd;
            float ll = (lr >= 0.f) ? lr : NEGS * lr;
            float t = tanh_xla(0.5f * ll);
            float attn = 0.5f * t + 0.5f;
            float sc = acc * attn;
            g_score[node] = sc;
            out_xs[node] = sc;
        }
    }
}

// per-graph top-K via bitonic 1024 (desc by score, ties asc by index)
__global__ void __launch_bounds__(1024) k_topk(float* __restrict__ out_perm) {
    __shared__ float skey[Nn];
    __shared__ int   sidx[Nn];
    int b = blockIdx.x, tid = threadIdx.x;
    skey[tid] = g_score[b * Nn + tid];
    sidx[tid] = tid;
    __syncthreads();
    for (int k = 2; k <= Nn; k <<= 1) {
        for (int j = k >> 1; j > 0; j >>= 1) {
            int i = tid, ixj = i ^ j;
            if (ixj > i) {
                float ka = skey[i], kb = skey[ixj];
                int ia = sidx[i], ib = sidx[ixj];
                bool up = ((i & k) == 0);
                bool bBeforeA = (kb > ka) || (kb == ka && ib < ia);
                bool aBeforeB = (ka > kb) || (ka == kb && ia < ib);
                bool sw = up ? bBeforeA : aBeforeB;
                if (sw) { skey[i] = kb; skey[ixj] = ka; sidx[i] = ib; sidx[ixj] = ia; }
            }
            __syncthreads();
        }
    }
    if (tid < KP) {
        int node = b * Nn + sidx[tid];
        int p = b * KP + tid;
        g_pnode[p] = node;
        g_mask[node] = p;
        out_perm[p] = (float)node;
    }
}

// direct-bucket CSR of valid pooled edges, grouped by pooled column
__global__ void __launch_bounds__(256) k_scatter2(const int* __restrict__ src,
                                                  const int* __restrict__ dst,
                                                  const float* __restrict__ ef) {
    int e = blockIdx.x * blockDim.x + threadIdx.x;
    if (e < ETOT) {
        int nr = g_mask[src[e]], nc = g_mask[dst[e]];
        if (nr >= 0 && nc >= 0) {
            int slot = atomicAdd(&g_cnt2[nc], 1);
            if (slot < CAP) {
                g2_row[nc * CAP + slot] = nr % KP;
                g2_val[nc * CAP + slot] = LAMBDA * ef[e];
            }
        }
    }
}

__global__ void __launch_bounds__(256) k_pool(const float* __restrict__ feat,
                                              const float* __restrict__ att,
                                              float* __restrict__ out_fp) {
    int p = (blockIdx.x * blockDim.x + threadIdx.x) >> 5;
    int lane = threadIdx.x & 31;
    if (p >= BK) return;
    int node = g_pnode[p];
    float4 fv = ((const float4*)(feat + (size_t)node * Dd))[lane];
    ((float4*)(out_fp + (size_t)p * Dd))[lane] = fv;
    float4 a1 = ((const float4*)att)[lane];
    float4 a2 = ((const float4*)(att + Dd))[lane];
    double s1 = (double)fv.x * a1.x + (double)fv.y * a1.y
              + (double)fv.z * a1.z + (double)fv.w * a1.w;
    double s2 = (double)fv.x * a2.x + (double)fv.y * a2.y
              + (double)fv.z * a2.z + (double)fv.w * a2.w;
    for (int o = 16; o; o >>= 1) {
        s1 += __shfl_xor_sync(0xffffffffu, s1, o);
        s2 += __shfl_xor_sync(0xffffffffu, s2, o);
    }
    if (lane == 0) { g_wsrc[p] = (float)s1; g_wdst[p] = (float)s2; }
}

// fused Wblk build + edge adds + sparsemax (Michelot, f32, warm start) + transposed write
__global__ void __launch_bounds__(256) k_spm(float* __restrict__ out_w) {
    __shared__ float sh[KP * SHP];
    int b = blockIdx.y;
    int j0 = blockIdx.x * TJ;
    int ncols = KP - j0; if (ncols > TJ) ncols = TJ;
    int t = threadIdx.x;
    int w = t & (TJ - 1), iq = t >> 3;
    int wp = t >> 5, lane = t & 31;

    if (w < ncols) {
        float wdj = g_wdst[(size_t)b * KP + j0 + w];
        for (int i = iq; i < KP; i += 32) {
            float v = g_wsrc[b * KP + i] + wdj;
            sh[i * SHP + w] = (v >= 0.f) ? v : NEGS * v;
        }
    }
    __syncthreads();

    if (wp < ncols) {
        int c = b * KP + j0 + wp;
        int cnt = g_cnt2[c]; if (cnt > CAP) cnt = CAP;
        int base = c * CAP;
        for (int e = lane; e < cnt; e += 32)
            atomicAdd(&sh[g2_row[base + e] * SHP + wp], g2_val[base + e]);
    }
    __syncthreads();

    if (wp < ncols) {
        float z[NQ];
        #pragma unroll
        for (int q = 0; q < NQ; q++) {
            int i = q * 32 + lane;
            z[q] = (i < KP) ? sh[i * SHP + wp] : -1e30f;
        }
        float s = 0.f, zmax = -1e30f;
        #pragma unroll
        for (int q = 0; q < NQ; q++) {
            int i = q * 32 + lane;
            if (i < KP) s += z[q];
            zmax = fmaxf(zmax, z[q]);
        }
        #pragma unroll
        for (int o = 16; o; o >>= 1) {
            s += __shfl_xor_sync(0xffffffffu, s, o);
            zmax = fmaxf(zmax, __shfl_xor_sync(0xffffffffu, zmax, o));
        }
        float tau = fmaxf((s - 1.f) / (float)KP, zmax - 1.f);
        int kprev = 0x7fffffff;
        for (int it = 0; it < 60; it++) {
            float s2 = 0.f; int k2 = 0;
            #pragma unroll
            for (int q = 0; q < NQ; q++) {
                float zz = z[q];
                if (zz > tau) { s2 += zz; k2++; }
            }
            #pragma unroll
            for (int o = 16; o; o >>= 1) {
                s2 += __shfl_xor_sync(0xffffffffu, s2, o);
                k2 += __shfl_xor_sync(0xffffffffu, k2, o);
            }
            if (k2 >= kprev || k2 == 0) break;
            float ntau = (s2 - 1.f) / (float)k2;
            if (ntau == tau) break;
            tau = ntau;
            kprev = k2;
        }
        #pragma unroll
        for (int q = 0; q < NQ; q++) {
            int i = q * 32 + lane;
            if (i < KP) {
                float d = z[q] - tau;
                sh[i * SHP + wp] = (d > 1e-9f) ? d : 0.f;
            }
        }
    }
    __syncthreads();

    {
        size_t base = (size_t)b * KP * KP;
        int j = j0 + w;
        if (j < KP && w < ncols) {
            for (int i = iq; i < KP; i += 32)
                out_w[base + (size_t)i * KP + j] = sh[i * SHP + w];
        }
    }
}

extern "C" void kernel_launch(void* const* d_in, const int* in_sizes, int n_in,
                              void* d_out, int out_size) {
    const float* feat = (const float*)d_in[0];
    const float* ef   = (const float*)d_in[1];
    const float* W    = (const float*)d_in[2];
    const float* a    = (const float*)d_in[3];
    const float* att  = (const float*)d_in[4];
    const int*   src  = (const int*)d_in[5];
    const int*   dst  = (const int*)d_in[6];

    float* out      = (float*)d_out;
    float* out_fp   = out;                               // [BK, D]
    float* out_w    = out + (size_t)BK * Dd;             // [B, KP, KP]
    float* out_perm = out_w + (size_t)BK * KP;           // [BK]
    float* out_xs   = out_perm + BK;                     // [NTOT]

    k_init<<<(NTOT + 255) / 256, 256>>>();                       // 1
    k_scatter1<<<(ETOT + 255) / 256, 256>>>(src, dst, ef);       // 2
    k_prep<<<16 + (NTOT + 255) / 256, 256>>>(W, a);              // 3
    k_node<<<NTOT / 2, 256>>>(feat, out_xs);                     // 4 <- ncu slot
    k_topk<<<Bg, 1024>>>(out_perm);
    k_scatter2<<<(ETOT + 255) / 256, 256>>>(src, dst, ef);
    k_pool<<<(BK * 32 + 255) / 256, 256>>>(feat, att, out_fp);

    dim3 g((KP + TJ - 1) / TJ, Bg);
    k_spm<<<g, 256>>>(out_w);
}

// round 14
// speedup vs baseline: 1.2762x; 1.2762x over previous
#include <cuda_runtime.h>
#include <math.h>
#include <stdint.h>

// ---- problem constants ----
#define Bg   64
#define Nn   1024
#define Dd   128
#define EPG  8192
#define NTOT (Bg*Nn)      // 65536
#define ETOT (Bg*EPG)     // 524288
#define KP   820          // kept nodes per graph
#define BK   (Bg*KP)      // 52480
#define NEGS 0.2f
#define LAMBDA 1.0f
#define TJ   8            // columns per sparsemax tile
#define SHP  9            // shared pitch (bank-conflict free)
#define NQ   26           // ceil(KP/32)
#define CAP  64           // bucket capacity (P(deg>=48) ~ 5e-15)

// ---- device scratch ----
__device__ int    g_cnt_out[NTOT];
__device__ int    g_cnt_in[NTOT];
__device__ float  g_sn[NTOT];
__device__ float  g_dn[NTOT];
__device__ float  g_fs[NTOT * Dd];   // feat * sn (ref's exact f32 intermediate)
__device__ int    g_csr_src[NTOT * CAP];
__device__ float  g_csr_val[NTOT * CAP];
__device__ double g_wa_d[Dd];
__device__ float  g_score[NTOT];
__device__ int    g_mask[NTOT];
__device__ float  g_wsrc[BK];
__device__ float  g_wdst[BK];
__device__ int    g_pnode[BK];
__device__ int    g_cnt2[BK];
__device__ int    g2_row[BK * CAP];
__device__ float  g2_val[BK * CAP];

// XLA f32 tanh (Eigen rational approximation, as emitted by XLA's elemental IR)
__device__ __forceinline__ float tanh_xla(float x) {
    float ax = fabsf(x);
    float cx = fminf(fmaxf(x, -7.90531110763549805f), 7.90531110763549805f);
    float x2 = cx * cx;
    float p = fmaf(x2, -2.76076847742355e-16f, 2.00018790482477e-13f);
    p = fmaf(p, x2, -8.60467152213735e-11f);
    p = fmaf(p, x2, 5.12229709037114e-08f);
    p = fmaf(p, x2, 1.48572235717979e-05f);
    p = fmaf(p, x2, 6.37261928875436e-04f);
    p = fmaf(p, x2, 4.89352455891786e-03f);
    p = p * cx;
    float q = fmaf(x2, 1.19825839466702e-06f, 1.18534705686654e-04f);
    q = fmaf(q, x2, 2.26843463243900e-03f);
    q = fmaf(q, x2, 4.89352518554385e-03f);
    float r = p / q;
    return (ax < 0.0004f) ? x : r;
}

__global__ void __launch_bounds__(256) k_init() {
    int i = blockIdx.x * blockDim.x + threadIdx.x;
    if (i < NTOT) { g_cnt_out[i] = 0; g_cnt_in[i] = 0; g_mask[i] = -1; }
    if (i < BK)   { g_cnt2[i] = 0; }
}

// fused degree count + direct-bucket CSR-by-dst scatter
__global__ void __launch_bounds__(256) k_scatter1(const int* __restrict__ src,
                                                  const int* __restrict__ dst,
                                                  const float* __restrict__ ef) {
    int e = blockIdx.x * blockDim.x + threadIdx.x;
    if (e < ETOT) {
        int dn = dst[e], sn = src[e];
        atomicAdd(&g_cnt_out[sn], 1);
        int slot = atomicAdd(&g_cnt_in[dn], 1);
        if (slot < CAP) {
            g_csr_src[dn * CAP + slot] = sn;
            g_csr_val[dn * CAP + slot] = (sn != dn) ? ef[e] : 0.0f;  // e_feat*nonself
        }
    }
}

// fused: wa = W@a (double, blocks 0..15) + deg^-0.5 (blocks 16..271)
__global__ void __launch_bounds__(256) k_prep(const float* __restrict__ W,
                                              const float* __restrict__ a) {
    if (blockIdx.x < 16) {
        int warp = (blockIdx.x * 256 + threadIdx.x) >> 5;
        int lane = threadIdx.x & 31;
        if (warp < Dd) {
            double s = 0.0;
            for (int k = lane; k < Dd; k += 32)
                s += (double)W[warp * Dd + k] * (double)a[k];
            #pragma unroll
            for (int o = 16; o; o >>= 1) s += __shfl_xor_sync(0xffffffffu, s, o);
            if (lane == 0) g_wa_d[warp] = s;
        }
    } else {
        int i = (blockIdx.x - 16) * 256 + threadIdx.x;
        if (i < NTOT) {
            double od = (double)max(g_cnt_out[i], 1);
            double id = (double)max(g_cnt_in[i], 1);
            g_sn[i] = (float)(1.0 / sqrt(od));
            g_dn[i] = (float)(1.0 / sqrt(id));
        }
    }
}

// dense stream: fs = feat * sn (f32, == ref's intermediate) — also warms L2
// with both feat and fs for the gather kernel that follows.
__global__ void __launch_bounds__(256) k_stream(const float* __restrict__ feat) {
    int i = blockIdx.x * blockDim.x + threadIdx.x;   // one float4 per thread
    if (i < NTOT * 32) {
        int row = i >> 5;
        float sn = g_sn[row];
        float4 f = ((const float4*)feat)[i];
        float4 r;
        r.x = f.x * sn; r.y = f.y * sn; r.z = f.z * sn; r.w = f.w * sn;
        ((float4*)g_fs)[i] = r;
    }
}

// k_node v6: R12's v3 shape, gathering precomputed fs (L2-hot, no sn in chain).
// float4 gathers; double accum layout {4L..4L+3}; exact double-shuffle
// redistribution to the XLA float2 layout -> bit-identical info tree + gate.
__global__ void __launch_bounds__(256) k_node(const float* __restrict__ feat,
                                              float* __restrict__ out_xs) {
    int gw = (blockIdx.x * blockDim.x + threadIdx.x) >> 5;
    int lane = threadIdx.x & 31;
    if (gw >= NTOT) return;
    int node = gw;
    float2 fva = ((const float2*)(feat + (size_t)node * Dd))[lane];        // 2L,2L+1
    float2 fvb = ((const float2*)(feat + (size_t)node * Dd + 64))[lane];   // 64+2L,65+2L
    double d0 = 0.0, d1 = 0.0, d2 = 0.0, d3 = 0.0;                          // 4L..4L+3
    int cnt = g_cnt_in[node]; if (cnt > CAP) cnt = CAP;
    int base = node * CAP;
    for (int p0 = 0; p0 < cnt; p0 += 4) {
        int m = cnt - p0; if (m > 4) m = 4;
        int sbuf[4]; float vbuf[4];
        #pragma unroll
        for (int t = 0; t < 4; t++) {
            sbuf[t] = (t < m) ? g_csr_src[base + p0 + t] : 0;
            vbuf[t] = (t < m) ? g_csr_val[base + p0 + t] : 0.f;
        }
        float4 f4[4];
        #pragma unroll
        for (int t = 0; t < 4; t++) {
            if (vbuf[t] != 0.f)
                f4[t] = ((const float4*)(g_fs + (size_t)sbuf[t] * Dd))[lane];
            else
                f4[t] = make_float4(0.f, 0.f, 0.f, 0.f);
        }
        #pragma unroll
        for (int t = 0; t < 4; t++) {
            if (vbuf[t] != 0.f) {
                float v = vbuf[t];
                d0 += (double)(f4[t].x * v);
                d1 += (double)(f4[t].y * v);
                d2 += (double)(f4[t].z * v);
                d3 += (double)(f4[t].w * v);
            }
        }
    }
    // exact redistribution: element e lives at lane e>>2, slot e&3
    int hl = lane >> 1;
    double s0a = __shfl_sync(0xffffffffu, d0, hl);
    double s1a = __shfl_sync(0xffffffffu, d1, hl);
    double s2a = __shfl_sync(0xffffffffu, d2, hl);
    double s3a = __shfl_sync(0xffffffffu, d3, hl);
    double s0b = __shfl_sync(0xffffffffu, d0, 16 + hl);
    double s1b = __shfl_sync(0xffffffffu, d1, 16 + hl);
    double s2b = __shfl_sync(0xffffffffu, d2, 16 + hl);
    double s3b = __shfl_sync(0xffffffffu, d3, 16 + hl);
    bool odd = (lane & 1) != 0;
    double ga0 = odd ? s2a : s0a;   // element 2L
    double ga1 = odd ? s3a : s1a;   // element 2L+1
    double gb0 = odd ? s2b : s0b;   // element 64+2L
    double gb1 = odd ? s3b : s1b;   // element 65+2L
    float dnf = g_dn[node];
    float g0 = (float)ga0, g1 = (float)ga1, g2v = (float)gb0, g3 = (float)gb1;
    float t0 = fabsf(fva.x - g0 * dnf);
    float t1 = fabsf(fva.y - g1 * dnf);
    float t2 = fabsf(fvb.x - g2v * dnf);
    float t3 = fabsf(fvb.y - g3 * dnf);
    float acc = ((t0 + t1) + t2) + t3;
    #pragma unroll
    for (int o = 16; o; o >>= 1)
        acc += __shfl_down_sync(0xffffffffu, acc, o);
    double dp_d = (double)fva.x * g_wa_d[2 * lane + 0]
                + (double)fva.y * g_wa_d[2 * lane + 1]
                + (double)fvb.x * g_wa_d[64 + 2 * lane + 0]
                + (double)fvb.y * g_wa_d[64 + 2 * lane + 1];
    #pragma unroll
    for (int o = 16; o; o >>= 1)
        dp_d += __shfl_xor_sync(0xffffffffu, dp_d, o);
    if (lane == 0) {
        float lr = (float)dp_d;
        float ll = (lr >= 0.f) ? lr : NEGS * lr;
        float t = tanh_xla(0.5f * ll);
        float attn = 0.5f * t + 0.5f;
        float sc = acc * attn;
        g_score[node] = sc;
        out_xs[node] = sc;
    }
}

// per-graph top-K via bitonic 1024 (desc by score, ties asc by index)
__global__ void __launch_bounds__(1024) k_topk(float* __restrict__ out_perm) {
    __shared__ float skey[Nn];
    __shared__ int   sidx[Nn];
    int b = blockIdx.x, tid = threadIdx.x;
    skey[tid] = g_score[b * Nn + tid];
    sidx[tid] = tid;
    __syncthreads();
    for (int k = 2; k <= Nn; k <<= 1) {
        for (int j = k >> 1; j > 0; j >>= 1) {
            int i = tid, ixj = i ^ j;
            if (ixj > i) {
                float ka = skey[i], kb = skey[ixj];
                int ia = sidx[i], ib = sidx[ixj];
                bool up = ((i & k) == 0);
                bool bBeforeA = (kb > ka) || (kb == ka && ib < ia);
                bool aBeforeB = (ka > kb) || (ka == kb && ia < ib);
                bool sw = up ? bBeforeA : aBeforeB;
                if (sw) { skey[i] = kb; skey[ixj] = ka; sidx[i] = ib; sidx[ixj] = ia; }
            }
            __syncthreads();
        }
    }
    if (tid < KP) {
        int node = b * Nn + sidx[tid];
        int p = b * KP + tid;
        g_pnode[p] = node;
        g_mask[node] = p;
        out_perm[p] = (float)node;
    }
}

// direct-bucket CSR of valid pooled edges, grouped by pooled column
__global__ void __launch_bounds__(256) k_scatter2(const int* __restrict__ src,
                                                  const int* __restrict__ dst,
                                                  const float* __restrict__ ef) {
    int e = blockIdx.x * blockDim.x + threadIdx.x;
    if (e < ETOT) {
        int nr = g_mask[src[e]], nc = g_mask[dst[e]];
        if (nr >= 0 && nc >= 0) {
            int slot = atomicAdd(&g_cnt2[nc], 1);
            if (slot < CAP) {
                g2_row[nc * CAP + slot] = nr % KP;
                g2_val[nc * CAP + slot] = LAMBDA * ef[e];
            }
        }
    }
}

__global__ void __launch_bounds__(256) k_pool(const float* __restrict__ feat,
                                              const float* __restrict__ att,
                                              float* __restrict__ out_fp) {
    int p = (blockIdx.x * blockDim.x + threadIdx.x) >> 5;
    int lane = threadIdx.x & 31;
    if (p >= BK) return;
    int node = g_pnode[p];
    float4 fv = ((const float4*)(feat + (size_t)node * Dd))[lane];
    ((float4*)(out_fp + (size_t)p * Dd))[lane] = fv;
    float4 a1 = ((const float4*)att)[lane];
    float4 a2 = ((const float4*)(att + Dd))[lane];
    double s1 = (double)fv.x * a1.x + (double)fv.y * a1.y
              + (double)fv.z * a1.z + (double)fv.w * a1.w;
    double s2 = (double)fv.x * a2.x + (double)fv.y * a2.y
              + (double)fv.z * a2.z + (double)fv.w * a2.w;
    for (int o = 16; o; o >>= 1) {
        s1 += __shfl_xor_sync(0xffffffffu, s1, o);
        s2 += __shfl_xor_sync(0xffffffffu, s2, o);
    }
    if (lane == 0) { g_wsrc[p] = (float)s1; g_wdst[p] = (float)s2; }
}

// fused Wblk build + edge adds + sparsemax (Michelot, f32, warm start) + transposed write
__global__ void __launch_bounds__(256) k_spm(float* __restrict__ out_w) {
    __shared__ float sh[KP * SHP];
    int b = blockIdx.y;
    int j0 = blockIdx.x * TJ;
    int ncols = KP - j0; if (ncols > TJ) ncols = TJ;
    int t = threadIdx.x;
    int w = t & (TJ - 1), iq = t >> 3;
    int wp = t >> 5, lane = t & 31;

    if (w < ncols) {
        float wdj = g_wdst[(size_t)b * KP + j0 + w];
        for (int i = iq; i < KP; i += 32) {
            float v = g_wsrc[b * KP + i] + wdj;
            sh[i * SHP + w] = (v >= 0.f) ? v : NEGS * v;
        }
    }
    __syncthreads();

    if (wp < ncols) {
        int c = b * KP + j0 + wp;
        int cnt = g_cnt2[c]; if (cnt > CAP) cnt = CAP;
        int base = c * CAP;
        for (int e = lane; e < cnt; e += 32)
            atomicAdd(&sh[g2_row[base + e] * SHP + wp], g2_val[base + e]);
    }
    __syncthreads();

    if (wp < ncols) {
        float z[NQ];
        #pragma unroll
        for (int q = 0; q < NQ; q++) {
            int i = q * 32 + lane;
            z[q] = (i < KP) ? sh[i * SHP + wp] : -1e30f;
        }
        float s = 0.f, zmax = -1e30f;
        #pragma unroll
        for (int q = 0; q < NQ; q++) {
            int i = q * 32 + lane;
            if (i < KP) s += z[q];
            zmax = fmaxf(zmax, z[q]);
        }
        #pragma unroll
        for (int o = 16; o; o >>= 1) {
            s += __shfl_xor_sync(0xffffffffu, s, o);
            zmax = fmaxf(zmax, __shfl_xor_sync(0xffffffffu, zmax, o));
        }
        float tau = fmaxf((s - 1.f) / (float)KP, zmax - 1.f);
        int kprev = 0x7fffffff;
        for (int it = 0; it < 60; it++) {
            float s2 = 0.f; int k2 = 0;
            #pragma unroll
            for (int q = 0; q < NQ; q++) {
                float zz = z[q];
                if (zz > tau) { s2 += zz; k2++; }
            }
            #pragma unroll
            for (int o = 16; o; o >>= 1) {
                s2 += __shfl_xor_sync(0xffffffffu, s2, o);
                k2 += __shfl_xor_sync(0xffffffffu, k2, o);
            }
            if (k2 >= kprev || k2 == 0) break;
            float ntau = (s2 - 1.f) / (float)k2;
            if (ntau == tau) break;
            tau = ntau;
            kprev = k2;
        }
        #pragma unroll
        for (int q = 0; q < NQ; q++) {
            int i = q * 32 + lane;
            if (i < KP) {
                float d = z[q] - tau;
                sh[i * SHP + wp] = (d > 1e-9f) ? d : 0.f;
            }
        }
    }
    __syncthreads();

    {
        size_t base = (size_t)b * KP * KP;
        int j = j0 + w;
        if (j < KP && w < ncols) {
            for (int i = iq; i < KP; i += 32)
                out_w[base + (size_t)i * KP + j] = sh[i * SHP + w];
        }
    }
}

extern "C" void kernel_launch(void* const* d_in, const int* in_sizes, int n_in,
                              void* d_out, int out_size) {
    const float* feat = (const float*)d_in[0];
    const float* ef   = (const float*)d_in[1];
    const float* W    = (const float*)d_in[2];
    const float* a    = (const float*)d_in[3];
    const float* att  = (const float*)d_in[4];
    const int*   src  = (const int*)d_in[5];
    const int*   dst  = (const int*)d_in[6];

    float* out      = (float*)d_out;
    float* out_fp   = out;                               // [BK, D]
    float* out_w    = out + (size_t)BK * Dd;             // [B, KP, KP]
    float* out_perm = out_w + (size_t)BK * KP;           // [BK]
    float* out_xs   = out_perm + BK;                     // [NTOT]

    k_init<<<(NTOT + 255) / 256, 256>>>();                       // 1
    k_scatter1<<<(ETOT + 255) / 256, 256>>>(src, dst, ef);       // 2
    k_prep<<<16 + (NTOT + 255) / 256, 256>>>(W, a);              // 3
    k_stream<<<(NTOT * 32 + 255) / 256, 256>>>(feat);            // 4 (warms L2)
    k_node<<<(NTOT * 32 + 255) / 256, 256>>>(feat, out_xs);      // 5
    k_topk<<<Bg, 1024>>>(out_perm);
    k_scatter2<<<(ETOT + 255) / 256, 256>>>(src, dst, ef);
    k_pool<<<(BK * 32 + 255) / 256, 256>>>(feat, att, out_fp);

    dim3 g((KP + TJ - 1) / TJ, Bg);
    k_spm<<<g, 256>>>(out_w);
}